// round 4
// baseline (speedup 1.0000x reference)
#include <cuda_runtime.h>
#include <cstdint>

// Problem constants
#define NVERT   20000
#define MTOT    40000          // B * NV
#define CDIM    64
#define NFDIM   128
#define KDIM    3072           // 3 rings * 16 dirs * 64 ch
#define NN      2048           // 128 f * 16 dout   (n = f*16 + dout)

// GEMM tiling — sized so static smem stays under the 48 KB no-opt-in limit
#define BM      128
#define BN      128
#define BK      16
#define NSTAGE  192            // KDIM / BK
#define LDS_PAD 20             // row stride in floats; lr*20 mod 32 hits 8 distinct
                               // 4-bank groups -> conflict-free fragment loads

// Rotation-expanded kernel, n-major: BexpT[n][k], n = f*16+dout, k = (r*16+s)*64+c
__device__ float g_BexpT[(size_t)NN * KDIM];

__global__ void build_bexp_kernel(const float* __restrict__ kern) {
    int tid = blockIdx.x * blockDim.x + threadIdx.x;
    if (tid >= NN * KDIM) return;
    int k = tid % KDIM;
    int n = tid / KDIM;
    int f    = n >> 4;
    int dout = n & 15;
    int rs = k >> 6, c = k & 63;
    int r = rs >> 4, s = rs & 15;
    int d = (s - dout) & 15;
    g_BexpT[tid] = kern[((r * 16 + d) * 64 + c) * 128 + f];
}

__device__ __forceinline__ uint32_t f2tf32(float x) {
    uint32_t u;
    asm("cvt.rna.tf32.f32 %0, %1;" : "=r"(u) : "f"(x));
    return u;
}

__device__ __forceinline__ void mma_tf32(float c[4], const uint32_t a[4],
                                         uint32_t b0, uint32_t b1) {
    asm volatile(
        "mma.sync.aligned.m16n8k8.row.col.f32.tf32.tf32.f32 "
        "{%0,%1,%2,%3},{%4,%5,%6,%7},{%8,%9},{%0,%1,%2,%3};"
        : "+f"(c[0]), "+f"(c[1]), "+f"(c[2]), "+f"(c[3])
        : "r"(a[0]), "r"(a[1]), "r"(a[2]), "r"(a[3]), "r"(b0), "r"(b1));
}

__device__ __forceinline__ void cpasync16(uint32_t dst, const void* src) {
    asm volatile("cp.async.cg.shared.global [%0], [%1], 16;" :: "r"(dst), "l"(src));
}

__global__ __launch_bounds__(256)
void gemm_kernel(const float* __restrict__ y, const int* __restrict__ em,
                 const float* __restrict__ bias, float* __restrict__ out) {
    // Static shared memory: 2 stages * (128 A-rows + 128 B-rows) * 20 floats
    // = 40960 bytes  (< 48 KB, so no cudaFuncSetAttribute needed -> graph-capturable)
    __shared__ float As[2][BM][LDS_PAD];
    __shared__ float Bs[2][BN][LDS_PAD];

    const int tid  = threadIdx.x;
    const int m0   = blockIdx.y * BM;
    const int n0   = blockIdx.x * BN;
    const int lane = tid & 31;
    const int warp = tid >> 5;
    const int wm   = warp & 3;     // 4 warps along M (32 rows each)
    const int wn   = warp >> 2;    // 2 warps along N (64 cols each)
    const int lr   = lane >> 2;
    const int lc   = lane & 3;

    // Precompute this thread's A-gather identity (threads 0..127 own A row=tid)
    int a_b = 0, a_v = 0;
    const bool isA = tid < BM;
    if (isA) {
        int m = m0 + tid;
        if (m >= MTOT) m = 0;              // clamp OOB rows to a safe read
        a_b = (m >= NVERT) ? 1 : 0;
        a_v = m - a_b * NVERT;
    }

    // ---- stage loader: one row (16 floats = 64 B = 4 x cp.async.16) per thread ----
    auto load_stage = [&](int ks, int stg) {
        if (isA) {
            const int rs    = ks >> 2;      // which (ring,dir) neighbor
            const int chunk = ks & 3;       // which 16-channel slice
            const int idx   = __ldg(&em[a_v * 48 + rs]);
            const float* src = y + (a_b * NVERT + idx) * CDIM + chunk * 16;
            uint32_t dst = (uint32_t)__cvta_generic_to_shared(&As[stg][tid][0]);
#pragma unroll
            for (int i = 0; i < 4; i++) cpasync16(dst + i * 16, src + i * 4);
        } else {
            const int row = tid - BM;
            const float* src = g_BexpT + (size_t)(n0 + row) * KDIM + ks * BK;
            uint32_t dst = (uint32_t)__cvta_generic_to_shared(&Bs[stg][row][0]);
#pragma unroll
            for (int i = 0; i < 4; i++) cpasync16(dst + i * 16, src + i * 4);
        }
        asm volatile("cp.async.commit_group;");
    };

    float acc[2][8][4];
#pragma unroll
    for (int mi = 0; mi < 2; mi++)
#pragma unroll
        for (int ni = 0; ni < 8; ni++)
#pragma unroll
            for (int j = 0; j < 4; j++) acc[mi][ni][j] = 0.0f;

    auto compute_stage = [&](int stg) {
#pragma unroll
        for (int kk = 0; kk < BK / 8; kk++) {
            const int kc = kk * 8 + lc;
            uint32_t a[2][4];
#pragma unroll
            for (int mi = 0; mi < 2; mi++) {
                const int rb = wm * 32 + mi * 16 + lr;
                a[mi][0] = f2tf32(As[stg][rb][kc]);
                a[mi][1] = f2tf32(As[stg][rb + 8][kc]);
                a[mi][2] = f2tf32(As[stg][rb][kc + 4]);
                a[mi][3] = f2tf32(As[stg][rb + 8][kc + 4]);
            }
#pragma unroll
            for (int ni = 0; ni < 8; ni++) {
                const int nb = wn * 64 + ni * 8 + lr;
                uint32_t b0 = f2tf32(Bs[stg][nb][kc]);
                uint32_t b1 = f2tf32(Bs[stg][nb][kc + 4]);
                mma_tf32(acc[0][ni], a[0], b0, b1);
                mma_tf32(acc[1][ni], a[1], b0, b1);
            }
        }
    };

    // ---- 2-stage cp.async pipeline over 192 K-stages ----
    load_stage(0, 0);
    load_stage(1, 1);
#pragma unroll 1
    for (int ks = 0; ks < NSTAGE; ks++) {
        if (ks < NSTAGE - 1) asm volatile("cp.async.wait_group 1;");
        else                 asm volatile("cp.async.wait_group 0;");
        __syncthreads();
        compute_stage(ks & 1);
        __syncthreads();
        if (ks + 2 < NSTAGE) load_stage(ks + 2, ks & 1);
    }

    // ---- fused epilogue: max over the 16 dout columns, +bias, relu ----
    // n = f*16 + dout, so each 16-wide group = two adjacent m16n8 tiles.
#pragma unroll
    for (int mi = 0; mi < 2; mi++) {
#pragma unroll
        for (int g = 0; g < 4; g++) {
            float lo = fmaxf(fmaxf(acc[mi][2 * g][0], acc[mi][2 * g][1]),
                             fmaxf(acc[mi][2 * g + 1][0], acc[mi][2 * g + 1][1]));
            float hi = fmaxf(fmaxf(acc[mi][2 * g][2], acc[mi][2 * g][3]),
                             fmaxf(acc[mi][2 * g + 1][2], acc[mi][2 * g + 1][3]));
            lo = fmaxf(lo, __shfl_xor_sync(0xffffffffu, lo, 1));
            lo = fmaxf(lo, __shfl_xor_sync(0xffffffffu, lo, 2));
            hi = fmaxf(hi, __shfl_xor_sync(0xffffffffu, hi, 1));
            hi = fmaxf(hi, __shfl_xor_sync(0xffffffffu, hi, 2));
            if (lc == 0) {
                const int f  = blockIdx.x * 8 + wn * 4 + g;
                const float bv = __ldg(&bias[f]);
                const int r0 = m0 + wm * 32 + mi * 16 + lr;
                const int r1 = r0 + 8;
                if (r0 < MTOT) out[r0 * NFDIM + f] = fmaxf(lo + bv, 0.0f);
                if (r1 < MTOT) out[r1 * NFDIM + f] = fmaxf(hi + bv, 0.0f);
            }
        }
    }
}

extern "C" void kernel_launch(void* const* d_in, const int* in_sizes, int n_in,
                              void* d_out, int out_size) {
    const float* y    = (const float*)d_in[0];
    const int*   em   = (const int*)d_in[1];
    const float* kern = (const float*)d_in[2];
    const float* bias = (const float*)d_in[3];
    float*       out  = (float*)d_out;

    // 1) expand kernel with all 16 circular rotations, transposed to n-major
    build_bexp_kernel<<<(NN * KDIM + 255) / 256, 256>>>(kern);

    // 2) fused gather-GEMM-relu-max:  C[40000, 2048] = gather(y) @ BexpT^T
    dim3 grid(NN / BN, (MTOT + BM - 1) / BM);   // (16, 313)
    gemm_kernel<<<grid, 256>>>(y, em, bias, out);
}

// round 7
// speedup vs baseline: 1.0753x; 1.0753x over previous
#include <cuda_runtime.h>
#include <cstdint>

// Problem constants
#define NVERT   20000
#define MTOT    40000          // B * NV
#define CDIM    64
#define NFDIM   128
#define KDIM    3072           // 3 rings * 16 dirs * 64 ch
#define NN      2048           // 128 f * 16 dout   (n = f*16 + dout)

// GEMM tiling — sized so static smem stays under the 48 KB no-opt-in limit
#define BM      128
#define BN      128
#define BK      16
#define NSTAGE  192            // KDIM / BK
#define LDS_PAD 20             // row pitch 80B: ldmatrix 8-row phases hit 8 disjoint
                               // 16B bank groups (20r mod 32 = 0,20,8,28,16,4,24,12)

// Rotation-expanded kernel, n-major, PRE-ROUNDED to tf32 bits:
//   BexpT[n][k], n = f*16+dout, k = (r*16+s)*64+c
__device__ float g_BexpT[(size_t)NN * KDIM];
// Pre-rounded (tf32) copy of y
__device__ float g_yr[(size_t)MTOT * CDIM];

__device__ __forceinline__ uint32_t f2tf32(float x) {
    uint32_t u;
    asm("cvt.rna.tf32.f32 %0, %1;" : "=r"(u) : "f"(x));
    return u;
}

__global__ void build_bexp_kernel(const float* __restrict__ kern) {
    int tid = blockIdx.x * blockDim.x + threadIdx.x;
    if (tid >= NN * KDIM) return;
    int k = tid % KDIM;
    int n = tid / KDIM;
    int f    = n >> 4;
    int dout = n & 15;
    int rs = k >> 6, c = k & 63;
    int r = rs >> 4, s = rs & 15;
    int d = (s - dout) & 15;
    g_BexpT[tid] = __uint_as_float(f2tf32(kern[((r * 16 + d) * 64 + c) * 128 + f]));
}

__global__ void round_y_kernel(const float* __restrict__ y) {
    int tid = blockIdx.x * blockDim.x + threadIdx.x;
    if (tid >= MTOT * CDIM) return;
    g_yr[tid] = __uint_as_float(f2tf32(y[tid]));
}

__device__ __forceinline__ void mma_tf32(float c[4], const uint32_t a[4],
                                         uint32_t b0, uint32_t b1) {
    asm volatile(
        "mma.sync.aligned.m16n8k8.row.col.f32.tf32.tf32.f32 "
        "{%0,%1,%2,%3},{%4,%5,%6,%7},{%8,%9},{%0,%1,%2,%3};"
        : "+f"(c[0]), "+f"(c[1]), "+f"(c[2]), "+f"(c[3])
        : "r"(a[0]), "r"(a[1]), "r"(a[2]), "r"(a[3]), "r"(b0), "r"(b1));
}

__device__ __forceinline__ void ldsm4(uint32_t& r0, uint32_t& r1,
                                      uint32_t& r2, uint32_t& r3, uint32_t addr) {
    asm volatile("ldmatrix.sync.aligned.m8n8.x4.shared.b16 {%0,%1,%2,%3}, [%4];"
                 : "=r"(r0), "=r"(r1), "=r"(r2), "=r"(r3) : "r"(addr));
}

__device__ __forceinline__ void cpasync16(uint32_t dst, const void* src) {
    asm volatile("cp.async.cg.shared.global [%0], [%1], 16;" :: "r"(dst), "l"(src));
}

__global__ __launch_bounds__(256)
void gemm_kernel(const float* __restrict__ em_dummy, const int* __restrict__ em,
                 const float* __restrict__ bias, float* __restrict__ out) {
    // Static shared memory: 40960 bytes (< 48 KB -> graph-capturable, no attribute call)
    __shared__ float As[2][BM][LDS_PAD];
    __shared__ float Bs[2][BN][LDS_PAD];

    const int tid  = threadIdx.x;
    const int m0   = blockIdx.y * BM;
    const int n0   = blockIdx.x * BN;
    const int lane = tid & 31;
    const int warp = tid >> 5;
    const int wm   = warp & 3;     // 4 warps along M (32 rows each)
    const int wn   = warp >> 2;    // 2 warps along N (64 cols each)
    const int lr   = lane >> 2;
    const int lc   = lane & 3;

    // ldmatrix lane -> (matrix, row) decomposition
    const int q  = lane >> 3;          // which 8x8 matrix (0..3)
    const int L  = lane & 7;           // row within the matrix
    const int qr = (q & 1) * 8 + L;    // row offset within a 16-row tile
    const int qc = (q >> 1) * 4;       // k offset: 0 or 4

    // Per-thread ldmatrix base addresses (stage 0); stage 1 adds STG_OFF bytes
    const uint32_t STG_OFF = BM * LDS_PAD * 4;  // 10240
    uint32_t aAddr[2], bAddr[4];
#pragma unroll
    for (int mi = 0; mi < 2; mi++)
        aAddr[mi] = (uint32_t)__cvta_generic_to_shared(
            &As[0][wm * 32 + mi * 16 + qr][qc]);
#pragma unroll
    for (int p = 0; p < 4; p++)
        bAddr[p] = (uint32_t)__cvta_generic_to_shared(
            &Bs[0][wn * 64 + p * 16 + qr][qc]);

    // Precompute this thread's A-gather identity (threads 0..127 own A row=tid)
    int a_b = 0, a_v = 0;
    const bool isA = tid < BM;
    if (isA) {
        int m = m0 + tid;
        if (m >= MTOT) m = 0;              // clamp OOB rows to a safe read
        a_b = (m >= NVERT) ? 1 : 0;
        a_v = m - a_b * NVERT;
    }

    // ---- stage loader: one row (16 floats = 64 B = 4 x cp.async.16) per thread ----
    auto load_stage = [&](int ks, int stg) {
        if (isA) {
            const int rs    = ks >> 2;      // which (ring,dir) neighbor
            const int chunk = ks & 3;       // which 16-channel slice
            const int idx   = __ldg(&em[a_v * 48 + rs]);
            const float* src = g_yr + (size_t)(a_b * NVERT + idx) * CDIM + chunk * 16;
            uint32_t dst = (uint32_t)__cvta_generic_to_shared(&As[stg][tid][0]);
#pragma unroll
            for (int i = 0; i < 4; i++) cpasync16(dst + i * 16, src + i * 4);
        } else {
            const int row = tid - BM;
            const float* src = g_BexpT + (size_t)(n0 + row) * KDIM + ks * BK;
            uint32_t dst = (uint32_t)__cvta_generic_to_shared(&Bs[stg][row][0]);
#pragma unroll
            for (int i = 0; i < 4; i++) cpasync16(dst + i * 16, src + i * 4);
        }
        asm volatile("cp.async.commit_group;");
    };

    float acc[2][8][4];
#pragma unroll
    for (int mi = 0; mi < 2; mi++)
#pragma unroll
        for (int ni = 0; ni < 8; ni++)
#pragma unroll
            for (int j = 0; j < 4; j++) acc[mi][ni][j] = 0.0f;

    auto compute_stage = [&](int stg) {
        const uint32_t so = stg ? STG_OFF : 0;
#pragma unroll
        for (int kk = 0; kk < BK / 8; kk++) {
            const uint32_t ko = so + kk * 32;   // 8 tf32 = 32 bytes along k
            uint32_t a[2][4];
            ldsm4(a[0][0], a[0][1], a[0][2], a[0][3], aAddr[0] + ko);
            ldsm4(a[1][0], a[1][1], a[1][2], a[1][3], aAddr[1] + ko);
#pragma unroll
            for (int p = 0; p < 4; p++) {
                uint32_t b00, b01, b10, b11;   // {b0 of ni=2p, b0 of 2p+1, b1 of 2p, b1 of 2p+1}
                ldsm4(b00, b01, b10, b11, bAddr[p] + ko);
                mma_tf32(acc[0][2 * p],     a[0], b00, b10);
                mma_tf32(acc[0][2 * p + 1], a[0], b01, b11);
                mma_tf32(acc[1][2 * p],     a[1], b00, b10);
                mma_tf32(acc[1][2 * p + 1], a[1], b01, b11);
            }
        }
    };

    // ---- 2-stage cp.async pipeline over 192 K-stages ----
    load_stage(0, 0);
    load_stage(1, 1);
#pragma unroll 1
    for (int ks = 0; ks < NSTAGE; ks++) {
        if (ks < NSTAGE - 1) asm volatile("cp.async.wait_group 1;");
        else                 asm volatile("cp.async.wait_group 0;");
        __syncthreads();
        compute_stage(ks & 1);
        __syncthreads();
        if (ks + 2 < NSTAGE) load_stage(ks + 2, ks & 1);
    }

    // ---- fused epilogue: max over the 16 dout columns, +bias, relu ----
#pragma unroll
    for (int mi = 0; mi < 2; mi++) {
#pragma unroll
        for (int g = 0; g < 4; g++) {
            float lo = fmaxf(fmaxf(acc[mi][2 * g][0], acc[mi][2 * g][1]),
                             fmaxf(acc[mi][2 * g + 1][0], acc[mi][2 * g + 1][1]));
            float hi = fmaxf(fmaxf(acc[mi][2 * g][2], acc[mi][2 * g][3]),
                             fmaxf(acc[mi][2 * g + 1][2], acc[mi][2 * g + 1][3]));
            lo = fmaxf(lo, __shfl_xor_sync(0xffffffffu, lo, 1));
            lo = fmaxf(lo, __shfl_xor_sync(0xffffffffu, lo, 2));
            hi = fmaxf(hi, __shfl_xor_sync(0xffffffffu, hi, 1));
            hi = fmaxf(hi, __shfl_xor_sync(0xffffffffu, hi, 2));
            if (lc == 0) {
                const int f  = blockIdx.x * 8 + wn * 4 + g;
                const float bv = __ldg(&bias[f]);
                const int r0 = m0 + wm * 32 + mi * 16 + lr;
                const int r1 = r0 + 8;
                if (r0 < MTOT) out[r0 * NFDIM + f] = fmaxf(lo + bv, 0.0f);
                if (r1 < MTOT) out[r1 * NFDIM + f] = fmaxf(hi + bv, 0.0f);
            }
        }
    }
}

extern "C" void kernel_launch(void* const* d_in, const int* in_sizes, int n_in,
                              void* d_out, int out_size) {
    const float* y    = (const float*)d_in[0];
    const int*   em   = (const int*)d_in[1];
    const float* kern = (const float*)d_in[2];
    const float* bias = (const float*)d_in[3];
    float*       out  = (float*)d_out;

    // 1) expand kernel with all 16 circular rotations (pre-rounded to tf32),
    //    and pre-round y — mainloop then needs zero cvt instructions
    build_bexp_kernel<<<(NN * KDIM + 255) / 256, 256>>>(kern);
    round_y_kernel<<<(MTOT * CDIM + 255) / 256, 256>>>(y);

    // 2) fused gather-GEMM-relu-max:  C[40000, 2048] = gather(y) @ BexpT^T
    dim3 grid(NN / BN, (MTOT + BM - 1) / BM);   // (16, 313)
    gemm_kernel<<<grid, 256>>>(nullptr, em, bias, out);
}

// round 9
// speedup vs baseline: 1.0941x; 1.0174x over previous
#include <cuda_runtime.h>
#include <cstdint>

// Problem constants
#define NVERT   20000
#define MTOT    40000          // B * NV
#define CDIM    64
#define NFDIM   128
#define KDIM    3072           // 3 rings * 16 dirs * 64 ch
#define NN      2048           // 128 f * 16 dout   (n = f*16 + dout)

// GEMM tiling
#define BM      128
#define BN      128
#define BK      16             // 64 B per row, no padding (XOR swizzle)
#define NSTAGE  192            // KDIM / BK
#define NPIPE   3              // 3-stage cp.async pipeline
#define TILE_B  (BM * BK * 4)  // 8192 bytes per operand tile per stage

// Rotation-expanded kernel, n-major, PRE-ROUNDED to tf32 bits
__device__ float g_BexpT[(size_t)NN * KDIM];
// Pre-rounded (tf32) copy of y
__device__ float g_yr[(size_t)MTOT * CDIM];

__device__ __forceinline__ uint32_t f2tf32(float x) {
    uint32_t u;
    asm("cvt.rna.tf32.f32 %0, %1;" : "=r"(u) : "f"(x));
    return u;
}

__global__ void build_bexp_kernel(const float* __restrict__ kern) {
    int tid = blockIdx.x * blockDim.x + threadIdx.x;
    if (tid >= NN * KDIM) return;
    int k = tid % KDIM;
    int n = tid / KDIM;
    int f    = n >> 4;
    int dout = n & 15;
    int rs = k >> 6, c = k & 63;
    int r = rs >> 4, s = rs & 15;
    int d = (s - dout) & 15;
    g_BexpT[tid] = __uint_as_float(f2tf32(kern[((r * 16 + d) * 64 + c) * 128 + f]));
}

__global__ void round_y_kernel(const float* __restrict__ y) {
    int tid = blockIdx.x * blockDim.x + threadIdx.x;
    if (tid >= MTOT * CDIM) return;
    g_yr[tid] = __uint_as_float(f2tf32(y[tid]));
}

__device__ __forceinline__ void mma_tf32(float c[4], const uint32_t a[4],
                                         uint32_t b0, uint32_t b1) {
    asm volatile(
        "mma.sync.aligned.m16n8k8.row.col.f32.tf32.tf32.f32 "
        "{%0,%1,%2,%3},{%4,%5,%6,%7},{%8,%9},{%0,%1,%2,%3};"
        : "+f"(c[0]), "+f"(c[1]), "+f"(c[2]), "+f"(c[3])
        : "r"(a[0]), "r"(a[1]), "r"(a[2]), "r"(a[3]), "r"(b0), "r"(b1));
}

__device__ __forceinline__ void ldsm4(uint32_t& r0, uint32_t& r1,
                                      uint32_t& r2, uint32_t& r3, uint32_t addr) {
    asm volatile("ldmatrix.sync.aligned.m8n8.x4.shared.b16 {%0,%1,%2,%3}, [%4];"
                 : "=r"(r0), "=r"(r1), "=r"(r2), "=r"(r3) : "r"(addr));
}

__device__ __forceinline__ void cpasync16(uint32_t dst, const void* src) {
    asm volatile("cp.async.cg.shared.global [%0], [%1], 16;" :: "r"(dst), "l"(src));
}

// XOR swizzle: 16B chunk c of row r lives at chunk position c ^ ((r>>1)&3).
// Every ldmatrix 8-row phase (consecutive rows, fixed c) then hits the 8
// distinct 16B bank-groups: position (4*(r&1) + (c ^ ((r>>1)&3))) mod 8.

__global__ __launch_bounds__(256)
void gemm_kernel(const float* __restrict__ em_dummy, const int* __restrict__ em,
                 const float* __restrict__ bias, float* __restrict__ out) {
    // Static smem: 3 stages * (8 KB A + 8 KB B) = 49152 B (= 48 KB limit, capturable)
    __shared__ float As[NPIPE][BM][BK];
    __shared__ float Bs[NPIPE][BN][BK];

    const int tid  = threadIdx.x;
    const int m0   = blockIdx.y * BM;
    const int n0   = blockIdx.x * BN;
    const int lane = tid & 31;
    const int warp = tid >> 5;
    const int wm   = warp & 3;     // 4 warps along M (32 rows each)
    const int wn   = warp >> 2;    // 2 warps along N (64 cols each)
    const int lr   = lane >> 2;
    const int lc   = lane & 3;

    // ldmatrix lane -> (matrix, row) decomposition
    const int q   = lane >> 3;         // which 8x8 matrix (0..3)
    const int L   = lane & 7;          // row within the matrix
    const int qr  = (q & 1) * 8 + L;   // row offset within a 16-row tile
    const int qhi = q >> 1;            // 16B chunk offset along k: 0 or 1

    // Per-thread ldmatrix addresses, fully precomputed per (tile, kk):
    //   addr = rowbase + ((chunk ^ sw(row)) << 4),  chunk = 2*kk + qhi
    uint32_t aAddr[2][2], bAddr[4][2];
#pragma unroll
    for (int mi = 0; mi < 2; mi++) {
        const int row = wm * 32 + mi * 16 + qr;
        const uint32_t base = (uint32_t)__cvta_generic_to_shared(&As[0][row][0]);
        const int sw = (row >> 1) & 3;
#pragma unroll
        for (int kk = 0; kk < 2; kk++)
            aAddr[mi][kk] = base + (uint32_t)(((2 * kk + qhi) ^ sw) << 4);
    }
#pragma unroll
    for (int p = 0; p < 4; p++) {
        const int row = wn * 64 + p * 16 + qr;
        const uint32_t base = (uint32_t)__cvta_generic_to_shared(&Bs[0][row][0]);
        const int sw = (row >> 1) & 3;
#pragma unroll
        for (int kk = 0; kk < 2; kk++)
            bAddr[p][kk] = base + (uint32_t)(((2 * kk + qhi) ^ sw) << 4);
    }

    // A-gather identity (threads 0..127 own A row=tid; 128..255 own B row=tid-128)
    int a_b = 0, a_v = 0;
    const bool isA = tid < BM;
    if (isA) {
        int m = m0 + tid;
        if (m >= MTOT) m = 0;
        a_b = (m >= NVERT) ? 1 : 0;
        a_v = m - a_b * NVERT;
    }
    const int ldRow = isA ? tid : (tid - BM);
    const int ldSw  = (ldRow >> 1) & 3;
    const uint32_t ldBase = isA
        ? (uint32_t)__cvta_generic_to_shared(&As[0][ldRow][0])
        : (uint32_t)__cvta_generic_to_shared(&Bs[0][ldRow][0]);

    // ---- stage loader: one 64 B row per thread, 4 swizzled 16 B chunks ----
    auto load_stage = [&](int ks, int slot) {
        const float* src;
        if (isA) {
            const int rs    = ks >> 2;
            const int chunk = ks & 3;
            const int idx   = __ldg(&em[a_v * 48 + rs]);
            src = g_yr + (size_t)(a_b * NVERT + idx) * CDIM + chunk * 16;
        } else {
            src = g_BexpT + (size_t)(n0 + ldRow) * KDIM + ks * BK;
        }
        const uint32_t dst = ldBase + (uint32_t)(slot * TILE_B);
#pragma unroll
        for (int i = 0; i < 4; i++)
            cpasync16(dst + ((i ^ ldSw) << 4), src + i * 4);
        asm volatile("cp.async.commit_group;");
    };

    float acc[2][8][4];
#pragma unroll
    for (int mi = 0; mi < 2; mi++)
#pragma unroll
        for (int ni = 0; ni < 8; ni++)
#pragma unroll
            for (int j = 0; j < 4; j++) acc[mi][ni][j] = 0.0f;

    auto compute_stage = [&](int slot) {
        const uint32_t so = (uint32_t)(slot * TILE_B);
#pragma unroll
        for (int kk = 0; kk < 2; kk++) {
            uint32_t a[2][4];
            ldsm4(a[0][0], a[0][1], a[0][2], a[0][3], aAddr[0][kk] + so);
            ldsm4(a[1][0], a[1][1], a[1][2], a[1][3], aAddr[1][kk] + so);
#pragma unroll
            for (int p = 0; p < 4; p++) {
                uint32_t b00, b01, b10, b11;
                ldsm4(b00, b01, b10, b11, bAddr[p][kk] + so);
                mma_tf32(acc[0][2 * p],     a[0], b00, b10);
                mma_tf32(acc[0][2 * p + 1], a[0], b01, b11);
                mma_tf32(acc[1][2 * p],     a[1], b00, b10);
                mma_tf32(acc[1][2 * p + 1], a[1], b01, b11);
            }
        }
    };

    // ---- 3-stage cp.async pipeline, ONE barrier per stage ----
    load_stage(0, 0);
    load_stage(1, 1);
    int cs = 0;   // slot of stage ks
#pragma unroll 1
    for (int ks = 0; ks < NSTAGE; ks++) {
        if (ks < NSTAGE - 1) asm volatile("cp.async.wait_group 1;");
        else                 asm volatile("cp.async.wait_group 0;");
        __syncthreads();
        // Load ks+2 into slot (ks+2)%3 == slot computed in iteration ks-1:
        // the barrier above guarantees all warps finished reading it.
        if (ks + 2 < NSTAGE) {
            int ls = cs + 2; if (ls >= NPIPE) ls -= NPIPE;
            load_stage(ks + 2, ls);
        }
        compute_stage(cs);
        if (++cs == NPIPE) cs = 0;
    }

    // ---- fused epilogue: max over the 16 dout columns, +bias, relu ----
#pragma unroll
    for (int mi = 0; mi < 2; mi++) {
#pragma unroll
        for (int g = 0; g < 4; g++) {
            float lo = fmaxf(fmaxf(acc[mi][2 * g][0], acc[mi][2 * g][1]),
                             fmaxf(acc[mi][2 * g + 1][0], acc[mi][2 * g + 1][1]));
            float hi = fmaxf(fmaxf(acc[mi][2 * g][2], acc[mi][2 * g][3]),
                             fmaxf(acc[mi][2 * g + 1][2], acc[mi][2 * g + 1][3]));
            lo = fmaxf(lo, __shfl_xor_sync(0xffffffffu, lo, 1));
            lo = fmaxf(lo, __shfl_xor_sync(0xffffffffu, lo, 2));
            hi = fmaxf(hi, __shfl_xor_sync(0xffffffffu, hi, 1));
            hi = fmaxf(hi, __shfl_xor_sync(0xffffffffu, hi, 2));
            if (lc == 0) {
                const int f  = blockIdx.x * 8 + wn * 4 + g;
                const float bv = __ldg(&bias[f]);
                const int r0 = m0 + wm * 32 + mi * 16 + lr;
                const int r1 = r0 + 8;
                if (r0 < MTOT) out[r0 * NFDIM + f] = fmaxf(lo + bv, 0.0f);
                if (r1 < MTOT) out[r1 * NFDIM + f] = fmaxf(hi + bv, 0.0f);
            }
        }
    }
}

extern "C" void kernel_launch(void* const* d_in, const int* in_sizes, int n_in,
                              void* d_out, int out_size) {
    const float* y    = (const float*)d_in[0];
    const int*   em   = (const int*)d_in[1];
    const float* kern = (const float*)d_in[2];
    const float* bias = (const float*)d_in[3];
    float*       out  = (float*)d_out;

    build_bexp_kernel<<<(NN * KDIM + 255) / 256, 256>>>(kern);
    round_y_kernel<<<(MTOT * CDIM + 255) / 256, 256>>>(y);

    dim3 grid(NN / BN, (MTOT + BM - 1) / BM);   // (16, 313)
    gemm_kernel<<<grid, 256>>>(nullptr, em, bias, out);
}

// round 11
// speedup vs baseline: 2.1691x; 1.9827x over previous
#include <cuda_runtime.h>
#include <cuda_fp16.h>
#include <cstdint>

// Problem constants
#define NVERT   20000
#define MTOT    40000          // B * NV
#define CDIM    64
#define NFDIM   128
#define KDIM    3072           // 3 rings * 16 dirs * 64 ch
#define NN      2048           // 128 f * 16 dout   (n = f*16 + dout)

// GEMM tiling — fp16 operands, mma.m16n8k16
#define BM      128
#define BN      128
#define BK      32             // 32 halves = 64 B per row, XOR-swizzled
#define NSTAGE  96             // KDIM / BK
#define NPIPE   3
#define TILE_B  (BM * BK * 2)  // 8192 bytes per operand tile per stage

// Rotation-expanded kernel (fp16, n-major) and fp16 copy of y
__device__ __half g_Bh[(size_t)NN * KDIM];
__device__ __half g_yh[(size_t)MTOT * CDIM];

__global__ void build_bexp_kernel(const float* __restrict__ kern) {
    int tid = blockIdx.x * blockDim.x + threadIdx.x;
    if (tid >= NN * KDIM) return;
    int k = tid % KDIM;
    int n = tid / KDIM;
    int f    = n >> 4;
    int dout = n & 15;
    int rs = k >> 6, c = k & 63;
    int r = rs >> 4, s = rs & 15;
    int d = (s - dout) & 15;
    g_Bh[tid] = __float2half_rn(kern[((r * 16 + d) * 64 + c) * 128 + f]);
}

__global__ void conv_y_kernel(const float* __restrict__ y) {
    int tid = blockIdx.x * blockDim.x + threadIdx.x;
    if (tid >= MTOT * CDIM) return;
    g_yh[tid] = __float2half_rn(y[tid]);
}

__device__ __forceinline__ void mma_f16(float c[4], const uint32_t a[4],
                                        uint32_t b0, uint32_t b1) {
    asm volatile(
        "mma.sync.aligned.m16n8k16.row.col.f32.f16.f16.f32 "
        "{%0,%1,%2,%3},{%4,%5,%6,%7},{%8,%9},{%0,%1,%2,%3};"
        : "+f"(c[0]), "+f"(c[1]), "+f"(c[2]), "+f"(c[3])
        : "r"(a[0]), "r"(a[1]), "r"(a[2]), "r"(a[3]), "r"(b0), "r"(b1));
}

__device__ __forceinline__ void ldsm4(uint32_t& r0, uint32_t& r1,
                                      uint32_t& r2, uint32_t& r3, uint32_t addr) {
    asm volatile("ldmatrix.sync.aligned.m8n8.x4.shared.b16 {%0,%1,%2,%3}, [%4];"
                 : "=r"(r0), "=r"(r1), "=r"(r2), "=r"(r3) : "r"(addr));
}

__device__ __forceinline__ void cpasync16(uint32_t dst, const void* src) {
    asm volatile("cp.async.cg.shared.global [%0], [%1], 16;" :: "r"(dst), "l"(src));
}

// XOR swizzle: 16B chunk c of row r lives at chunk position c ^ ((r>>1)&3).
// Every ldmatrix 8-row phase hits 8 distinct 16B bank-groups.

__global__ __launch_bounds__(256)
void gemm_kernel(const float* __restrict__ dummy, const int* __restrict__ em,
                 const float* __restrict__ bias, float* __restrict__ out) {
    // Static smem: 3 stages * (8 KB A + 8 KB B) = 49152 B (= 48 KB, capturable)
    __shared__ __half As[NPIPE][BM][BK];
    __shared__ __half Bs[NPIPE][BN][BK];

    const int tid  = threadIdx.x;
    const int m0   = blockIdx.y * BM;
    const int n0   = blockIdx.x * BN;
    const int lane = tid & 31;
    const int warp = tid >> 5;
    const int wm   = warp & 3;     // 4 warps along M (32 rows each)
    const int wn   = warp >> 2;    // 2 warps along N (64 cols each)
    const int lr   = lane >> 2;
    const int lc   = lane & 3;

    // ldmatrix lane -> (matrix, row) decomposition
    const int q   = lane >> 3;         // which 8x8 matrix (0..3)
    const int L   = lane & 7;          // row within the matrix
    const int qr  = (q & 1) * 8 + L;   // row offset within a 16-row tile
    const int qhi = q >> 1;            // 16B chunk (k8 halves) offset: 0 or 1

    // Per-thread ldmatrix addresses per (tile, k16-step):
    //   addr = rowbase + ((chunk ^ sw(row)) << 4),  chunk = 2*kk + qhi
    uint32_t aAddr[2][2], bAddr[4][2];
#pragma unroll
    for (int mi = 0; mi < 2; mi++) {
        const int row = wm * 32 + mi * 16 + qr;
        const uint32_t base = (uint32_t)__cvta_generic_to_shared(&As[0][row][0]);
        const int sw = (row >> 1) & 3;
#pragma unroll
        for (int kk = 0; kk < 2; kk++)
            aAddr[mi][kk] = base + (uint32_t)(((2 * kk + qhi) ^ sw) << 4);
    }
#pragma unroll
    for (int p = 0; p < 4; p++) {
        const int row = wn * 64 + p * 16 + qr;
        const uint32_t base = (uint32_t)__cvta_generic_to_shared(&Bs[0][row][0]);
        const int sw = (row >> 1) & 3;
#pragma unroll
        for (int kk = 0; kk < 2; kk++)
            bAddr[p][kk] = base + (uint32_t)(((2 * kk + qhi) ^ sw) << 4);
    }

    // A-gather identity (threads 0..127 own A row=tid; 128..255 own B row=tid-128)
    int a_b = 0, a_v = 0;
    const bool isA = tid < BM;
    if (isA) {
        int m = m0 + tid;
        if (m >= MTOT) m = 0;
        a_b = (m >= NVERT) ? 1 : 0;
        a_v = m - a_b * NVERT;
    }
    const int ldRow = isA ? tid : (tid - BM);
    const int ldSw  = (ldRow >> 1) & 3;
    const uint32_t ldBase = isA
        ? (uint32_t)__cvta_generic_to_shared(&As[0][ldRow][0])
        : (uint32_t)__cvta_generic_to_shared(&Bs[0][ldRow][0]);

    // ---- stage loader: one 64 B row per thread, 4 swizzled 16 B chunks ----
    auto load_stage = [&](int ks, int slot) {
        const __half* src;
        if (isA) {
            const int rs = ks >> 1;              // (ring,dir) neighbor, 0..47
            const int ch = ks & 1;               // which 32-channel half
            const int idx = __ldg(&em[a_v * 48 + rs]);
            src = g_yh + (size_t)(a_b * NVERT + idx) * CDIM + ch * 32;
        } else {
            src = g_Bh + (size_t)(n0 + ldRow) * KDIM + ks * BK;
        }
        const uint32_t dst = ldBase + (uint32_t)(slot * TILE_B);
#pragma unroll
        for (int i = 0; i < 4; i++)
            cpasync16(dst + ((i ^ ldSw) << 4), src + i * 8);
        asm volatile("cp.async.commit_group;");
    };

    float acc[2][8][4];
#pragma unroll
    for (int mi = 0; mi < 2; mi++)
#pragma unroll
        for (int ni = 0; ni < 8; ni++)
#pragma unroll
            for (int j = 0; j < 4; j++) acc[mi][ni][j] = 0.0f;

    auto compute_stage = [&](int slot) {
        const uint32_t so = (uint32_t)(slot * TILE_B);
#pragma unroll
        for (int kk = 0; kk < 2; kk++) {         // two k16 steps per BK=32 stage
            uint32_t a[2][4];
            ldsm4(a[0][0], a[0][1], a[0][2], a[0][3], aAddr[0][kk] + so);
            ldsm4(a[1][0], a[1][1], a[1][2], a[1][3], aAddr[1][kk] + so);
#pragma unroll
            for (int p = 0; p < 4; p++) {
                uint32_t b00, b01, b10, b11;   // {b0 n-lo, b0 n-hi, b1 n-lo, b1 n-hi}
                ldsm4(b00, b01, b10, b11, bAddr[p][kk] + so);
                mma_f16(acc[0][2 * p],     a[0], b00, b10);
                mma_f16(acc[0][2 * p + 1], a[0], b01, b11);
                mma_f16(acc[1][2 * p],     a[1], b00, b10);
                mma_f16(acc[1][2 * p + 1], a[1], b01, b11);
            }
        }
    };

    // ---- 3-stage cp.async pipeline, ONE barrier per stage ----
    load_stage(0, 0);
    load_stage(1, 1);
    int cs = 0;   // slot of stage ks
#pragma unroll 1
    for (int ks = 0; ks < NSTAGE; ks++) {
        if (ks < NSTAGE - 1) asm volatile("cp.async.wait_group 1;");
        else                 asm volatile("cp.async.wait_group 0;");
        __syncthreads();
        if (ks + 2 < NSTAGE) {
            int ls = cs + 2; if (ls >= NPIPE) ls -= NPIPE;
            load_stage(ks + 2, ls);
        }
        compute_stage(cs);
        if (++cs == NPIPE) cs = 0;
    }

    // ---- fused epilogue: max over the 16 dout columns, +bias, relu ----
#pragma unroll
    for (int mi = 0; mi < 2; mi++) {
#pragma unroll
        for (int g = 0; g < 4; g++) {
            float lo = fmaxf(fmaxf(acc[mi][2 * g][0], acc[mi][2 * g][1]),
                             fmaxf(acc[mi][2 * g + 1][0], acc[mi][2 * g + 1][1]));
            float hi = fmaxf(fmaxf(acc[mi][2 * g][2], acc[mi][2 * g][3]),
                             fmaxf(acc[mi][2 * g + 1][2], acc[mi][2 * g + 1][3]));
            lo = fmaxf(lo, __shfl_xor_sync(0xffffffffu, lo, 1));
            lo = fmaxf(lo, __shfl_xor_sync(0xffffffffu, lo, 2));
            hi = fmaxf(hi, __shfl_xor_sync(0xffffffffu, hi, 1));
            hi = fmaxf(hi, __shfl_xor_sync(0xffffffffu, hi, 2));
            if (lc == 0) {
                const int f  = blockIdx.x * 8 + wn * 4 + g;
                const float bv = __ldg(&bias[f]);
                const int r0 = m0 + wm * 32 + mi * 16 + lr;
                const int r1 = r0 + 8;
                if (r0 < MTOT) out[r0 * NFDIM + f] = fmaxf(lo + bv, 0.0f);
                if (r1 < MTOT) out[r1 * NFDIM + f] = fmaxf(hi + bv, 0.0f);
            }
        }
    }
}

extern "C" void kernel_launch(void* const* d_in, const int* in_sizes, int n_in,
                              void* d_out, int out_size) {
    const float* y    = (const float*)d_in[0];
    const int*   em   = (const int*)d_in[1];
    const float* kern = (const float*)d_in[2];
    const float* bias = (const float*)d_in[3];
    float*       out  = (float*)d_out;

    // prep: rotation-expanded fp16 kernel (n-major) + fp16 copy of y
    build_bexp_kernel<<<(NN * KDIM + 255) / 256, 256>>>(kern);
    conv_y_kernel<<<(MTOT * CDIM + 255) / 256, 256>>>(y);

    // fused gather-GEMM-relu-max:  C[40000, 2048] = gather(y) @ Bh^T
    dim3 grid(NN / BN, (MTOT + BM - 1) / BM);   // (16, 313)
    gemm_kernel<<<grid, 256>>>(nullptr, em, bias, out);
}

// round 12
// speedup vs baseline: 2.8276x; 1.3035x over previous
#include <cuda_runtime.h>
#include <cuda_fp16.h>
#include <cstdint>

// Problem constants
#define NVERT   20000
#define MTOT    40000          // B * NV
#define CDIM    64
#define NFDIM   128
#define KDIM    3072           // 3 rings * 16 dirs * 64 ch
#define NN      2048           // 128 f * 16 dout   (n = f*16 + dout)

// GEMM tiling — fp16 operands, mma.m16n8k16, 512 threads (16 warps, 4Mx4N)
#define BM      128
#define BN      128
#define BK      32             // 32 halves = 64 B per row, XOR-swizzled
#define NSTAGE  96             // KDIM / BK
#define NPIPE   3
#define TILE_B  (BM * BK * 2)  // 8192 bytes per operand tile per stage

// Rotation-expanded kernel (fp16, n-major) and fp16 copy of y
__device__ __half g_Bh[(size_t)NN * KDIM];
__device__ __half g_yh[(size_t)MTOT * CDIM];

__global__ void build_bexp_kernel(const float* __restrict__ kern) {
    int tid = blockIdx.x * blockDim.x + threadIdx.x;
    if (tid >= NN * KDIM) return;
    int k = tid % KDIM;
    int n = tid / KDIM;
    int f    = n >> 4;
    int dout = n & 15;
    int rs = k >> 6, c = k & 63;
    int r = rs >> 4, s = rs & 15;
    int d = (s - dout) & 15;
    g_Bh[tid] = __float2half_rn(kern[((r * 16 + d) * 64 + c) * 128 + f]);
}

__global__ void conv_y_kernel(const float* __restrict__ y) {
    int tid = blockIdx.x * blockDim.x + threadIdx.x;
    if (tid >= MTOT * CDIM) return;
    g_yh[tid] = __float2half_rn(y[tid]);
}

__device__ __forceinline__ void mma_f16(float c[4], const uint32_t a[4],
                                        uint32_t b0, uint32_t b1) {
    asm volatile(
        "mma.sync.aligned.m16n8k16.row.col.f32.f16.f16.f32 "
        "{%0,%1,%2,%3},{%4,%5,%6,%7},{%8,%9},{%0,%1,%2,%3};"
        : "+f"(c[0]), "+f"(c[1]), "+f"(c[2]), "+f"(c[3])
        : "r"(a[0]), "r"(a[1]), "r"(a[2]), "r"(a[3]), "r"(b0), "r"(b1));
}

__device__ __forceinline__ void ldsm4(uint32_t& r0, uint32_t& r1,
                                      uint32_t& r2, uint32_t& r3, uint32_t addr) {
    asm volatile("ldmatrix.sync.aligned.m8n8.x4.shared.b16 {%0,%1,%2,%3}, [%4];"
                 : "=r"(r0), "=r"(r1), "=r"(r2), "=r"(r3) : "r"(addr));
}

__device__ __forceinline__ void cpasync16(uint32_t dst, const void* src) {
    asm volatile("cp.async.cg.shared.global [%0], [%1], 16;" :: "r"(dst), "l"(src));
}

// XOR swizzle: 16B chunk c of row r lives at chunk position c ^ ((r>>1)&3).
// Every ldmatrix 8-row phase hits 8 distinct 16B bank-groups.

__global__ __launch_bounds__(512, 2)
void gemm_kernel(const float* __restrict__ dummy, const int* __restrict__ em,
                 const float* __restrict__ bias, float* __restrict__ out) {
    // Static smem: 3 stages * (8 KB A + 8 KB B) = 49152 B (= 48 KB, capturable)
    __shared__ __half As[NPIPE][BM][BK];
    __shared__ __half Bs[NPIPE][BN][BK];

    const int tid  = threadIdx.x;
    const int m0   = blockIdx.y * BM;
    const int n0   = blockIdx.x * BN;
    const int lane = tid & 31;
    const int warp = tid >> 5;
    const int wm   = warp & 3;     // 4 warps along M (32 rows each)
    const int wn   = warp >> 2;    // 4 warps along N (32 cols each)
    const int lr   = lane >> 2;
    const int lc   = lane & 3;

    // ldmatrix lane -> (matrix, row) decomposition
    const int q   = lane >> 3;         // which 8x8 matrix (0..3)
    const int L   = lane & 7;          // row within the matrix
    const int qr  = (q & 1) * 8 + L;   // row offset within a 16-row tile
    const int qhi = q >> 1;            // 16B chunk (k8 halves) offset: 0 or 1

    // Per-thread ldmatrix addresses per (tile, k16-step):
    //   addr = rowbase + ((chunk ^ sw(row)) << 4),  chunk = 2*kk + qhi
    uint32_t aAddr[2][2], bAddr[2][2];
#pragma unroll
    for (int mi = 0; mi < 2; mi++) {
        const int row = wm * 32 + mi * 16 + qr;
        const uint32_t base = (uint32_t)__cvta_generic_to_shared(&As[0][row][0]);
        const int sw = (row >> 1) & 3;
#pragma unroll
        for (int kk = 0; kk < 2; kk++)
            aAddr[mi][kk] = base + (uint32_t)(((2 * kk + qhi) ^ sw) << 4);
    }
#pragma unroll
    for (int p = 0; p < 2; p++) {
        const int row = wn * 32 + p * 16 + qr;
        const uint32_t base = (uint32_t)__cvta_generic_to_shared(&Bs[0][row][0]);
        const int sw = (row >> 1) & 3;
#pragma unroll
        for (int kk = 0; kk < 2; kk++)
            bAddr[p][kk] = base + (uint32_t)(((2 * kk + qhi) ^ sw) << 4);
    }

    // Loader identity: 512 threads, 2 threads per 64 B row (2 x 16 B chunks each).
    // tids 0..255 -> A rows, 256..511 -> B rows.
    const bool isA  = tid < 2 * BM;
    const int  pr   = isA ? tid : (tid - 2 * BM);
    const int  ldRow = pr >> 1;
    const int  half  = pr & 1;          // which 32 B half of the row
    const int  ldSw  = (ldRow >> 1) & 3;
    int a_b = 0, a_v = 0;
    if (isA) {
        int m = m0 + ldRow;
        if (m >= MTOT) m = 0;
        a_b = (m >= NVERT) ? 1 : 0;
        a_v = m - a_b * NVERT;
    }
    const uint32_t ldBase = isA
        ? (uint32_t)__cvta_generic_to_shared(&As[0][ldRow][0])
        : (uint32_t)__cvta_generic_to_shared(&Bs[0][ldRow][0]);

    // ---- stage loader: 2 swizzled 16 B chunks per thread ----
    auto load_stage = [&](int ks, int slot) {
        const __half* src;
        if (isA) {
            const int rs = ks >> 1;              // (ring,dir) neighbor, 0..47
            const int ch = ks & 1;               // which 32-channel half
            const int idx = __ldg(&em[a_v * 48 + rs]);
            src = g_yh + (size_t)(a_b * NVERT + idx) * CDIM + ch * 32;
        } else {
            src = g_Bh + (size_t)(n0 + ldRow) * KDIM + ks * BK;
        }
        const uint32_t dst = ldBase + (uint32_t)(slot * TILE_B);
#pragma unroll
        for (int i = 0; i < 2; i++) {
            const int c = 2 * half + i;
            cpasync16(dst + ((c ^ ldSw) << 4), src + c * 8);
        }
        asm volatile("cp.async.commit_group;");
    };

    float acc[2][4][4];
#pragma unroll
    for (int mi = 0; mi < 2; mi++)
#pragma unroll
        for (int ni = 0; ni < 4; ni++)
#pragma unroll
            for (int j = 0; j < 4; j++) acc[mi][ni][j] = 0.0f;

    auto compute_stage = [&](int slot) {
        const uint32_t so = (uint32_t)(slot * TILE_B);
#pragma unroll
        for (int kk = 0; kk < 2; kk++) {         // two k16 steps per BK=32 stage
            uint32_t a[2][4];
            ldsm4(a[0][0], a[0][1], a[0][2], a[0][3], aAddr[0][kk] + so);
            ldsm4(a[1][0], a[1][1], a[1][2], a[1][3], aAddr[1][kk] + so);
#pragma unroll
            for (int p = 0; p < 2; p++) {
                uint32_t b00, b01, b10, b11;   // {b0 n-lo, b0 n-hi, b1 n-lo, b1 n-hi}
                ldsm4(b00, b01, b10, b11, bAddr[p][kk] + so);
                mma_f16(acc[0][2 * p],     a[0], b00, b10);
                mma_f16(acc[0][2 * p + 1], a[0], b01, b11);
                mma_f16(acc[1][2 * p],     a[1], b00, b10);
                mma_f16(acc[1][2 * p + 1], a[1], b01, b11);
            }
        }
    };

    // ---- 3-stage cp.async pipeline, ONE barrier per stage ----
    load_stage(0, 0);
    load_stage(1, 1);
    int cs = 0;   // slot of stage ks
#pragma unroll 1
    for (int ks = 0; ks < NSTAGE; ks++) {
        if (ks < NSTAGE - 1) asm volatile("cp.async.wait_group 1;");
        else                 asm volatile("cp.async.wait_group 0;");
        __syncthreads();
        if (ks + 2 < NSTAGE) {
            int ls = cs + 2; if (ls >= NPIPE) ls -= NPIPE;
            load_stage(ks + 2, ls);
        }
        compute_stage(cs);
        if (++cs == NPIPE) cs = 0;
    }

    // ---- fused epilogue: max over the 16 dout columns, +bias, relu ----
    // Warp covers 32 N-cols = 2 f-groups (16 cols each = n-tiles 2g, 2g+1).
#pragma unroll
    for (int mi = 0; mi < 2; mi++) {
#pragma unroll
        for (int g = 0; g < 2; g++) {
            float lo = fmaxf(fmaxf(acc[mi][2 * g][0], acc[mi][2 * g][1]),
                             fmaxf(acc[mi][2 * g + 1][0], acc[mi][2 * g + 1][1]));
            float hi = fmaxf(fmaxf(acc[mi][2 * g][2], acc[mi][2 * g][3]),
                             fmaxf(acc[mi][2 * g + 1][2], acc[mi][2 * g + 1][3]));
            lo = fmaxf(lo, __shfl_xor_sync(0xffffffffu, lo, 1));
            lo = fmaxf(lo, __shfl_xor_sync(0xffffffffu, lo, 2));
            hi = fmaxf(hi, __shfl_xor_sync(0xffffffffu, hi, 1));
            hi = fmaxf(hi, __shfl_xor_sync(0xffffffffu, hi, 2));
            if (lc == 0) {
                const int f  = blockIdx.x * 8 + wn * 2 + g;
                const float bv = __ldg(&bias[f]);
                const int r0 = m0 + wm * 32 + mi * 16 + lr;
                const int r1 = r0 + 8;
                if (r0 < MTOT) out[r0 * NFDIM + f] = fmaxf(lo + bv, 0.0f);
                if (r1 < MTOT) out[r1 * NFDIM + f] = fmaxf(hi + bv, 0.0f);
            }
        }
    }
}

extern "C" void kernel_launch(void* const* d_in, const int* in_sizes, int n_in,
                              void* d_out, int out_size) {
    const float* y    = (const float*)d_in[0];
    const int*   em   = (const int*)d_in[1];
    const float* kern = (const float*)d_in[2];
    const float* bias = (const float*)d_in[3];
    float*       out  = (float*)d_out;

    // prep: rotation-expanded fp16 kernel (n-major) + fp16 copy of y
    build_bexp_kernel<<<(NN * KDIM + 255) / 256, 256>>>(kern);
    conv_y_kernel<<<(MTOT * CDIM + 255) / 256, 256>>>(y);

    // fused gather-GEMM-relu-max:  C[40000, 2048] = gather(y) @ Bh^T
    dim3 grid(NN / BN, (MTOT + BM - 1) / BM);   // (16, 313)
    gemm_kernel<<<grid, 512>>>(nullptr, em, bias, out);
}

// round 15
// speedup vs baseline: 3.0843x; 1.0908x over previous
#include <cuda_runtime.h>
#include <cuda_fp16.h>
#include <cstdint>

// Problem constants
#define NVERT   20000
#define MTOT    40000          // B * NV
#define CDIM    64
#define NFDIM   128
#define KDIM    3072           // 3 rings * 16 dirs * 64 ch
#define NN      2048           // 128 f * 16 dout   (n = f*16 + dout)

// GEMM tiling — fp16 operands, mma.m16n8k16, 512 threads (16 warps, 4Mx4N)
#define BM      128
#define BN      128
#define BK      32             // 32 halves = 64 B per row, XOR-swizzled
#define NSTAGE  96             // KDIM / BK;  hot loop covers NSTAGE-3 = 93 = 31*3
#define NPIPE   3
#define TILE_B  (BM * BK * 2)  // 8192 bytes per operand tile per stage

// Rotation-expanded kernel (fp16, n-major) and fp16 copy of y
__device__ __half g_Bh[(size_t)NN * KDIM];
__device__ __half g_yh[(size_t)MTOT * CDIM];

__global__ void build_bexp_kernel(const float* __restrict__ kern) {
    int tid = blockIdx.x * blockDim.x + threadIdx.x;
    if (tid >= NN * KDIM) return;
    int k = tid % KDIM;
    int n = tid / KDIM;
    int f    = n >> 4;
    int dout = n & 15;
    int rs = k >> 6, c = k & 63;
    int r = rs >> 4, s = rs & 15;
    int d = (s - dout) & 15;
    g_Bh[tid] = __float2half_rn(kern[((r * 16 + d) * 64 + c) * 128 + f]);
}

__global__ void conv_y_kernel(const float* __restrict__ y) {
    int tid = blockIdx.x * blockDim.x + threadIdx.x;
    if (tid >= MTOT * CDIM) return;
    g_yh[tid] = __float2half_rn(y[tid]);
}

__device__ __forceinline__ void mma_f16(float c[4], const uint32_t a[4],
                                        uint32_t b0, uint32_t b1) {
    asm volatile(
        "mma.sync.aligned.m16n8k16.row.col.f32.f16.f16.f32 "
        "{%0,%1,%2,%3},{%4,%5,%6,%7},{%8,%9},{%0,%1,%2,%3};"
        : "+f"(c[0]), "+f"(c[1]), "+f"(c[2]), "+f"(c[3])
        : "r"(a[0]), "r"(a[1]), "r"(a[2]), "r"(a[3]), "r"(b0), "r"(b1));
}

__device__ __forceinline__ void ldsm4(uint32_t& r0, uint32_t& r1,
                                      uint32_t& r2, uint32_t& r3, uint32_t addr) {
    asm volatile("ldmatrix.sync.aligned.m8n8.x4.shared.b16 {%0,%1,%2,%3}, [%4];"
                 : "=r"(r0), "=r"(r1), "=r"(r2), "=r"(r3) : "r"(addr));
}

__device__ __forceinline__ void cpasync16(uint32_t dst, const void* src) {
    asm volatile("cp.async.cg.shared.global [%0], [%1], 16;" :: "r"(dst), "l"(src));
}

// XOR swizzle: 16B chunk c of row r lives at chunk position c ^ ((r>>1)&3).
// Every ldmatrix 8-row phase hits 8 distinct 16B bank-groups.
// kk toggles bit1 of the chunk, carry-free -> addr(kk=1) = addr(kk=0) ^ 32.

__global__ __launch_bounds__(512, 2)
void gemm_kernel(const float* __restrict__ dummy, const int* __restrict__ em,
                 const float* __restrict__ bias, float* __restrict__ out) {
    // Static smem: 3 stages * (8 KB A + 8 KB B) = 49152 B (= 48 KB, capturable)
    __shared__ __half As[NPIPE][BM][BK];
    __shared__ __half Bs[NPIPE][BN][BK];

    const int tid  = threadIdx.x;
    const int m0   = blockIdx.y * BM;
    const int n0   = blockIdx.x * BN;
    const int lane = tid & 31;
    const int warp = tid >> 5;
    const int wm   = warp & 3;     // 4 warps along M (32 rows each)
    const int wn   = warp >> 2;    // 4 warps along N (32 cols each)
    const int lr   = lane >> 2;
    const int lc   = lane & 3;

    // ldmatrix lane -> (matrix, row) decomposition
    const int q   = lane >> 3;         // which 8x8 matrix (0..3)
    const int L   = lane & 7;          // row within the matrix
    const int qr  = (q & 1) * 8 + L;   // row offset within a 16-row tile
    const int qhi = q >> 1;            // 16B chunk (k8 halves) offset: 0 or 1

    // Per-thread ldmatrix base addresses (kk=0); kk=1 is base ^ 32.
    uint32_t aAddr[2], bAddr[2];
#pragma unroll
    for (int mi = 0; mi < 2; mi++) {
        const int row = wm * 32 + mi * 16 + qr;
        const int sw = (row >> 1) & 3;
        aAddr[mi] = (uint32_t)__cvta_generic_to_shared(&As[0][row][0])
                  + (uint32_t)((qhi ^ sw) << 4);
    }
#pragma unroll
    for (int p = 0; p < 2; p++) {
        const int row = wn * 32 + p * 16 + qr;
        const int sw = (row >> 1) & 3;
        bAddr[p] = (uint32_t)__cvta_generic_to_shared(&Bs[0][row][0])
                 + (uint32_t)((qhi ^ sw) << 4);
    }

    // Loader identity: 2 threads per 64 B row (2 x 16 B chunks each).
    // tids 0..255 -> A rows, 256..511 -> B rows.
    const bool isA  = tid < 2 * BM;
    const int  pr    = isA ? tid : (tid - 2 * BM);
    const int  ldRow = pr >> 1;
    const int  half  = pr & 1;
    const int  ldSw  = (ldRow >> 1) & 3;
    int a_b = 0, a_v = 0;
    if (isA) {
        int m = m0 + ldRow;
        if (m >= MTOT) m = 0;
        a_b = (m >= NVERT) ? 1 : 0;
        a_v = m - a_b * NVERT;
    }
    const uint32_t ldBase = isA
        ? (uint32_t)__cvta_generic_to_shared(&As[0][ldRow][0])
        : (uint32_t)__cvta_generic_to_shared(&Bs[0][ldRow][0]);

    auto load_stage = [&](int ks, int slot) {
        const __half* src;
        if (isA) {
            const int rs = ks >> 1;
            const int ch = ks & 1;
            const int idx = __ldg(&em[a_v * 48 + rs]);
            src = g_yh + (size_t)(a_b * NVERT + idx) * CDIM + ch * 32;
        } else {
            src = g_Bh + (size_t)(n0 + ldRow) * KDIM + ks * BK;
        }
        const uint32_t dst = ldBase + (uint32_t)(slot * TILE_B);
#pragma unroll
        for (int i = 0; i < 2; i++) {
            const int c = 2 * half + i;
            cpasync16(dst + ((c ^ ldSw) << 4), src + c * 8);
        }
        asm volatile("cp.async.commit_group;");
    };

    float acc[2][4][4];
#pragma unroll
    for (int mi = 0; mi < 2; mi++)
#pragma unroll
        for (int ni = 0; ni < 4; ni++)
#pragma unroll
            for (int j = 0; j < 4; j++) acc[mi][ni][j] = 0.0f;

    auto compute_stage = [&](int slot) {
        const uint32_t so = (uint32_t)(slot * TILE_B);
#pragma unroll
        for (int kk = 0; kk < 2; kk++) {         // kk=1 address = kk=0 ^ 32
            const uint32_t kx = (uint32_t)(kk << 5);
            uint32_t a[2][4];
            ldsm4(a[0][0], a[0][1], a[0][2], a[0][3], (aAddr[0] ^ kx) + so);
            ldsm4(a[1][0], a[1][1], a[1][2], a[1][3], (aAddr[1] ^ kx) + so);
#pragma unroll
            for (int p = 0; p < 2; p++) {
                uint32_t b00, b01, b10, b11;
                ldsm4(b00, b01, b10, b11, (bAddr[p] ^ kx) + so);
                mma_f16(acc[0][2 * p],     a[0], b00, b10);
                mma_f16(acc[0][2 * p + 1], a[0], b01, b11);
                mma_f16(acc[1][2 * p],     a[1], b00, b10);
                mma_f16(acc[1][2 * p + 1], a[1], b01, b11);
            }
        }
    };

    // ---- 3-stage cp.async pipeline, ONE barrier per stage ----
    load_stage(0, 0);
    load_stage(1, 1);

    // Hot loop: stages 0..92 (93 = 31 groups of 3; slots are compile-time j).
    // Stage ks: wait for load ks, barrier, prefetch ks+2 (max 94), compute.
#pragma unroll 1
    for (int ks = 0; ks < NSTAGE - 3; ks += NPIPE) {
#pragma unroll
        for (int j = 0; j < NPIPE; j++) {
            asm volatile("cp.async.wait_group 1;");
            __syncthreads();
            load_stage(ks + j + 2, (j + 2) % NPIPE);
            compute_stage(j);
        }
    }
    // Tail: stage 93 (slot 0) prefetches stage 95; stages 94, 95 compute only.
    asm volatile("cp.async.wait_group 1;");
    __syncthreads();
    load_stage(NSTAGE - 1, (NSTAGE - 1) % NPIPE);   // stage 95 -> slot 2
    compute_stage((NSTAGE - 3) % NPIPE);            // stage 93, slot 0
    asm volatile("cp.async.wait_group 1;");
    __syncthreads();
    compute_stage((NSTAGE - 2) % NPIPE);            // stage 94, slot 1
    asm volatile("cp.async.wait_group 0;");
    __syncthreads();
    compute_stage((NSTAGE - 1) % NPIPE);            // stage 95, slot 2

    // ---- fused epilogue: max over the 16 dout columns, +bias, relu ----
#pragma unroll
    for (int mi = 0; mi < 2; mi++) {
#pragma unroll
        for (int g = 0; g < 2; g++) {
            float lo = fmaxf(fmaxf(acc[mi][2 * g][0], acc[mi][2 * g][1]),
                             fmaxf(acc[mi][2 * g + 1][0], acc[mi][2 * g + 1][1]));
            float hi = fmaxf(fmaxf(acc[mi][2 * g][2], acc[mi][2 * g][3]),
                             fmaxf(acc[mi][2 * g + 1][2], acc[mi][2 * g + 1][3]));
            lo = fmaxf(lo, __shfl_xor_sync(0xffffffffu, lo, 1));
            lo = fmaxf(lo, __shfl_xor_sync(0xffffffffu, lo, 2));
            hi = fmaxf(hi, __shfl_xor_sync(0xffffffffu, hi, 1));
            hi = fmaxf(hi, __shfl_xor_sync(0xffffffffu, hi, 2));
            if (lc == 0) {
                const int f  = blockIdx.x * 8 + wn * 2 + g;
                const float bv = __ldg(&bias[f]);
                const int r0 = m0 + wm * 32 + mi * 16 + lr;
                const int r1 = r0 + 8;
                if (r0 < MTOT) out[r0 * NFDIM + f] = fmaxf(lo + bv, 0.0f);
                if (r1 < MTOT) out[r1 * NFDIM + f] = fmaxf(hi + bv, 0.0f);
            }
        }
    }
}

extern "C" void kernel_launch(void* const* d_in, const int* in_sizes, int n_in,
                              void* d_out, int out_size) {
    const float* y    = (const float*)d_in[0];
    const int*   em   = (const int*)d_in[1];
    const float* kern = (const float*)d_in[2];
    const float* bias = (const float*)d_in[3];
    float*       out  = (float*)d_out;

    // prep: rotation-expanded fp16 kernel (n-major) + fp16 copy of y
    build_bexp_kernel<<<(NN * KDIM + 255) / 256, 256>>>(kern);
    conv_y_kernel<<<(MTOT * CDIM + 255) / 256, 256>>>(y);

    // fused gather-GEMM-relu-max:  C[40000, 2048] = gather(y) @ Bh^T
    dim3 grid(NN / BN, (MTOT + BM - 1) / BM);   // (16, 313)
    gemm_kernel<<<grid, 512>>>(nullptr, em, bias, out);
}

// round 16
// speedup vs baseline: 3.2247x; 1.0455x over previous
#include <cuda_runtime.h>
#include <cuda_fp16.h>
#include <cstdint>

// Problem constants
#define NVERT   20000
#define MTOT    40000          // B * NV
#define CDIM    64
#define NFDIM   128
// Radix-2 split: K' = 3*8*64 = 1536, N' = 128 f * 8 d = 1024
#define KP      1536
#define NP      1024

#define BM      128
#define BNP     64             // CTA tile over N' (per part)
#define BK      16             // 16 halves = 32 B rows
#define NSTAGE  96             // KP / BK; hot loop 93 = 31*3
#define NPIPE   3

// Precomputed split kernels, n-major: Bp/Bm[n'][k'], n'=f*8+d, k'=(r*8+t)*64+c
//   Bp = (k[u]+k[u+8])/2,  Bm = eps(t,d)*(k[u]-k[u+8])/2,  u=(t-d)&7
__device__ __half g_Bp[(size_t)NP * KP];
__device__ __half g_Bm[(size_t)NP * KP];
__device__ __half g_yh[(size_t)MTOT * CDIM];

__global__ void build_b_split(const float* __restrict__ kern) {
    int tid = blockIdx.x * blockDim.x + threadIdx.x;
    if (tid >= NP * KP) return;
    int k = tid % KP;
    int n = tid / KP;
    int f = n >> 3, d = n & 7;
    int rt = k >> 6, c = k & 63;
    int r = rt >> 3, t = rt & 7;
    int u = (t - d) & 7;
    float klo = kern[((r * 16 + u) * 64 + c) * 128 + f];
    float khi = kern[((r * 16 + u + 8) * 64 + c) * 128 + f];
    g_Bp[tid] = __float2half_rn(0.5f * (klo + khi));
    float km = 0.5f * (klo - khi);
    g_Bm[tid] = __float2half_rn(t >= d ? km : -km);
}

__global__ void conv_y_kernel(const float* __restrict__ y) {
    int tid = blockIdx.x * blockDim.x + threadIdx.x;
    if (tid >= MTOT * CDIM) return;
    g_yh[tid] = __float2half_rn(y[tid]);
}

__device__ __forceinline__ void mma_f16(float c[4], const uint32_t a[4],
                                        uint32_t b0, uint32_t b1) {
    asm volatile(
        "mma.sync.aligned.m16n8k16.row.col.f32.f16.f16.f32 "
        "{%0,%1,%2,%3},{%4,%5,%6,%7},{%8,%9},{%0,%1,%2,%3};"
        : "+f"(c[0]), "+f"(c[1]), "+f"(c[2]), "+f"(c[3])
        : "r"(a[0]), "r"(a[1]), "r"(a[2]), "r"(a[3]), "r"(b0), "r"(b1));
}

__device__ __forceinline__ void ldsm4(uint32_t& r0, uint32_t& r1,
                                      uint32_t& r2, uint32_t& r3, uint32_t addr) {
    asm volatile("ldmatrix.sync.aligned.m8n8.x4.shared.b16 {%0,%1,%2,%3}, [%4];"
                 : "=r"(r0), "=r"(r1), "=r"(r2), "=r"(r3) : "r"(addr));
}

__device__ __forceinline__ void cpasync16(uint32_t dst, const void* src) {
    asm volatile("cp.async.cg.shared.global [%0], [%1], 16;" :: "r"(dst), "l"(src));
}

// 32B rows: 2 x 16B chunks; swizzle chunk ^= (row>>2)&1 makes every 8-row
// ldsm phase (and every 8-lane store phase) hit 8 distinct 16B bank groups.

struct SmemLayout {
    __half Ap[NPIPE][BM][BK];   // gp tiles  (12 KB)
    __half Am[NPIPE][BM][BK];   // gm tiles  (12 KB)
    __half Bp[NPIPE][BNP][BK];  // kp tiles  ( 6 KB)
    __half Bm[NPIPE][BNP][BK];  // km tiles  ( 6 KB)
};                              // total 36864 B; epilogue reuses 32 KB as scratch

#define A_SLOT 4096
#define B_SLOT 2048

__global__ __launch_bounds__(512, 2)
void gemm_kernel(const int* __restrict__ em, const float* __restrict__ bias,
                 float* __restrict__ out) {
    __shared__ __align__(16) SmemLayout sm;

    const int tid  = threadIdx.x;
    const int m0   = blockIdx.y * BM;
    const int n0p  = blockIdx.x * BNP;   // base n' = f*8+d
    const int lane = tid & 31;
    const int warp = tid >> 5;
    const int part = warp >> 3;          // 0 = cyclic (gp*kp), 1 = skew (gm*km)
    const int w8   = warp & 7;
    const int wm   = w8 & 3;             // 4 warps along M (32 rows)
    const int wn   = w8 >> 2;            // 2 warps along N' (32 cols)
    const int lr   = lane >> 2;
    const int lc   = lane & 3;

    // ldmatrix lane decomposition
    const int q   = lane >> 3;
    const int L   = lane & 7;
    const int qr  = (q & 1) * 8 + L;
    const int qhi = q >> 1;

    // Per-warp ldmatrix base addresses (slot 0)
    uint32_t aAddr[2], bAddr[2];
#pragma unroll
    for (int mi = 0; mi < 2; mi++) {
        const int row = wm * 32 + mi * 16 + qr;
        const __half* base = part ? &sm.Am[0][row][0] : &sm.Ap[0][row][0];
        aAddr[mi] = (uint32_t)__cvta_generic_to_shared(base)
                  + (uint32_t)((qhi ^ ((row >> 2) & 1)) << 4);
    }
#pragma unroll
    for (int p = 0; p < 2; p++) {
        const int row = wn * 32 + p * 16 + qr;
        const __half* base = part ? &sm.Bm[0][row][0] : &sm.Bp[0][row][0];
        bAddr[p] = (uint32_t)__cvta_generic_to_shared(base)
                 + (uint32_t)((qhi ^ ((row >> 2) & 1)) << 4);
    }

    // Loader identities.
    // tids 0..255: A rows (2 threads/row, 16B halves); 256..511: B chunks.
    const bool isA = tid < 256;
    const int  rowA = tid >> 1;
    const int  halfA = tid & 1;
    const int  chA = halfA ^ ((rowA >> 2) & 1);
    int a_b = 0, a_v = 0;
    if (isA) {
        int m = m0 + rowA;
        if (m >= MTOT) m = 0;
        a_b = (m >= NVERT) ? 1 : 0;
        a_v = m - a_b * NVERT;
    }
    const int qB    = tid - 256;
    const int partB = qB & 1;
    const int halfB = (qB >> 1) & 1;
    const int rowB  = qB >> 2;
    const int chB   = halfB ^ ((rowB >> 2) & 1);
    uint32_t dstB = 0;
    const __half* srcBbase = nullptr;
    if (!isA) {
        const __half* b0 = partB ? &sm.Bm[0][rowB][0] : &sm.Bp[0][rowB][0];
        dstB = (uint32_t)__cvta_generic_to_shared(b0) + (uint32_t)(chB << 4);
        srcBbase = (partB ? g_Bm : g_Bp) + (size_t)(n0p + rowB) * KP + halfB * 8;
    }

    auto load_stage = [&](int ks, int slot) {
        if (isA) {
            const int rt  = ks >> 2;
            const int c0  = (ks & 3) << 4;
            const int rti = (rt >> 3) * 16 + (rt & 7);      // r*16 + t
            const int i0  = __ldg(&em[a_v * 48 + rti]);
            const int i1  = __ldg(&em[a_v * 48 + rti + 8]);
            const uint4 d0 = *reinterpret_cast<const uint4*>(
                g_yh + (size_t)(a_b * NVERT + i0) * CDIM + c0 + halfA * 8);
            const uint4 d1 = *reinterpret_cast<const uint4*>(
                g_yh + (size_t)(a_b * NVERT + i1) * CDIM + c0 + halfA * 8);
            const __half2* h0 = reinterpret_cast<const __half2*>(&d0);
            const __half2* h1 = reinterpret_cast<const __half2*>(&d1);
            uint4 P, M;
            __half2* pp = reinterpret_cast<__half2*>(&P);
            __half2* pm = reinterpret_cast<__half2*>(&M);
#pragma unroll
            for (int i = 0; i < 4; i++) {
                pp[i] = __hadd2(h0[i], h1[i]);
                pm[i] = __hsub2(h0[i], h1[i]);
            }
            *reinterpret_cast<uint4*>(&sm.Ap[slot][rowA][chA * 8]) = P;
            *reinterpret_cast<uint4*>(&sm.Am[slot][rowA][chA * 8]) = M;
        } else {
            cpasync16(dstB + (uint32_t)(slot * B_SLOT), srcBbase + ks * BK);
        }
        asm volatile("cp.async.commit_group;");
    };

    float acc[2][4][4];
#pragma unroll
    for (int mi = 0; mi < 2; mi++)
#pragma unroll
        for (int ni = 0; ni < 4; ni++)
#pragma unroll
            for (int j = 0; j < 4; j++) acc[mi][ni][j] = 0.0f;

    auto compute_stage = [&](int slot) {
        const uint32_t ao = (uint32_t)(slot * A_SLOT);
        const uint32_t bo = (uint32_t)(slot * B_SLOT);
        uint32_t a[2][4];
        ldsm4(a[0][0], a[0][1], a[0][2], a[0][3], aAddr[0] + ao);
        ldsm4(a[1][0], a[1][1], a[1][2], a[1][3], aAddr[1] + ao);
#pragma unroll
        for (int p = 0; p < 2; p++) {
            uint32_t b00, b01, b10, b11;
            ldsm4(b00, b01, b10, b11, bAddr[p] + bo);
            mma_f16(acc[0][2 * p],     a[0], b00, b10);
            mma_f16(acc[0][2 * p + 1], a[0], b01, b11);
            mma_f16(acc[1][2 * p],     a[1], b00, b10);
            mma_f16(acc[1][2 * p + 1], a[1], b01, b11);
        }
    };

    // ---- 3-stage pipeline, ONE barrier per stage (R14-proven skeleton) ----
    load_stage(0, 0);
    load_stage(1, 1);
#pragma unroll 1
    for (int ks = 0; ks < NSTAGE - 3; ks += NPIPE) {
#pragma unroll
        for (int j = 0; j < NPIPE; j++) {
            asm volatile("cp.async.wait_group 1;");
            __syncthreads();
            load_stage(ks + j + 2, (j + 2) % NPIPE);
            compute_stage(j);
        }
    }
    asm volatile("cp.async.wait_group 1;");
    __syncthreads();
    load_stage(NSTAGE - 1, (NSTAGE - 1) % NPIPE);   // stage 95 -> slot 2
    compute_stage((NSTAGE - 3) % NPIPE);            // stage 93, slot 0
    asm volatile("cp.async.wait_group 1;");
    __syncthreads();
    compute_stage((NSTAGE - 2) % NPIPE);            // stage 94, slot 1
    asm volatile("cp.async.wait_group 0;");
    __syncthreads();
    compute_stage((NSTAGE - 1) % NPIPE);            // stage 95, slot 2

    // ---- epilogue: out = Cc + |Cn| (= max over all 16 douts), bias, relu ----
    float* scratch = reinterpret_cast<float*>(&sm);  // 32 KB needed, 36 KB free
    __syncthreads();
    if (part == 1) {
#pragma unroll
        for (int mi = 0; mi < 2; mi++)
#pragma unroll
            for (int ni = 0; ni < 4; ni++)
#pragma unroll
                for (int j = 0; j < 4; j++)
                    scratch[w8 * 1024 + (mi * 16 + ni * 4 + j) * 32 + lane] =
                        acc[mi][ni][j];
    }
    __syncthreads();
    if (part == 0) {
#pragma unroll
        for (int mi = 0; mi < 2; mi++) {
#pragma unroll
            for (int ni = 0; ni < 4; ni++) {
                float v[4];
#pragma unroll
                for (int j = 0; j < 4; j++)
                    v[j] = acc[mi][ni][j] + fabsf(
                        scratch[w8 * 1024 + (mi * 16 + ni * 4 + j) * 32 + lane]);
                float lo = fmaxf(v[0], v[1]);   // row lr,   d = 2lc, 2lc+1
                float hi = fmaxf(v[2], v[3]);   // row lr+8
                lo = fmaxf(lo, __shfl_xor_sync(0xffffffffu, lo, 1));
                lo = fmaxf(lo, __shfl_xor_sync(0xffffffffu, lo, 2));
                hi = fmaxf(hi, __shfl_xor_sync(0xffffffffu, hi, 1));
                hi = fmaxf(hi, __shfl_xor_sync(0xffffffffu, hi, 2));
                if (lc == 0) {
                    const int f = blockIdx.x * 8 + wn * 4 + ni;
                    const float bv = __ldg(&bias[f]);
                    const int r0 = m0 + wm * 32 + mi * 16 + lr;
                    const int r1 = r0 + 8;
                    if (r0 < MTOT) out[r0 * NFDIM + f] = fmaxf(lo + bv, 0.0f);
                    if (r1 < MTOT) out[r1 * NFDIM + f] = fmaxf(hi + bv, 0.0f);
                }
            }
        }
    }
}

extern "C" void kernel_launch(void* const* d_in, const int* in_sizes, int n_in,
                              void* d_out, int out_size) {
    const float* y    = (const float*)d_in[0];
    const int*   em   = (const int*)d_in[1];
    const float* kern = (const float*)d_in[2];
    const float* bias = (const float*)d_in[3];
    float*       out  = (float*)d_out;

    // prep: radix-2 split kernels (kp, eps*km, n-major) + fp16 copy of y
    build_b_split<<<(NP * KP + 255) / 256, 256>>>(kern);
    conv_y_kernel<<<(MTOT * CDIM + 255) / 256, 256>>>(y);

    // fused gather + split-GEMM + combine/max/relu
    dim3 grid(NP / BNP, (MTOT + BM - 1) / BM);   // (16, 313)
    gemm_kernel<<<grid, 512>>>(em, bias, out);
}